// round 17
// baseline (speedup 1.0000x reference)
#include <cuda_runtime.h>
#include <cuda_fp16.h>
#include <math.h>
#include <cstdint>

typedef unsigned long long u64;
typedef unsigned int u32;

#define BB 1024
#define TILES 8
#define NT 512
#define NCTA 128
#define EPSG 1e-5f
#define FULLM 0xffffffffu

// SMEM layout
#define H0B 0             // 64KB: h0 pair-buffers [wq][c][512B]
#define H1B 65536         // 64KB: h1 pair-buffers
#define B0_OFF 131072     // 32KB
#define B1_OFF 163840     // 64KB
#define SC_OFF 229376     // 1KB coords
#define SMEM_TOTAL 230400

// ---------------- global scratch ----------------
__device__ u64 g_frag0[16 * 4096];
__device__ u64 g_frag1[16 * 8192];
__device__ float4 g_epi[1024];
__device__ float  g_Wup[128 * 256];
__device__ float  g_hA1[256], g_hW1[256];
__device__ float  g_GAg[4], g_GWg[4], g_BAt[1], g_BWt[1];
__device__ uint4  g_h0frag[TILES * 16 * 256];       // frag cells [tile*16+q][m16*32+lane]
__device__ uint4  g_h1frag[2][TILES * 16 * 256];    // parity buffered
__device__ float4 g_part2[TILES * 128 * 32];        // [tile][row][q*2+wn]
__device__ float  g_h0f[TILES * 128 * 256];
__device__ unsigned g_flagA[TILES * 32];
__device__ unsigned g_flagB[TILES * 32];
__device__ unsigned g_barc[TILES * 32];

__device__ __forceinline__ float tanh_fast(float x) {
    float y; asm("tanh.approx.f32 %0, %1;" : "=f"(y) : "f"(x)); return y;
}
__device__ __forceinline__ float sig_fast(float x) {
    return 0.5f * tanh_fast(0.5f * x) + 0.5f;
}
__device__ __forceinline__ u32 smem_u32_of(const void* p) {
    u32 a;
    asm("{ .reg .u64 t; cvta.to.shared.u64 t, %1; cvt.u32.u64 %0, t; }" : "=r"(a) : "l"(p));
    return a;
}
#define CP16(dst, src) \
    asm volatile("cp.async.cg.shared.global [%0], [%1], 16;" :: "r"(dst), "l"(src))
#define CP_COMMIT()  asm volatile("cp.async.commit_group;" ::: "memory")
#define CP_WAITALL() asm volatile("cp.async.wait_all;" ::: "memory")
#define CP_WAITGRP(n) asm volatile("cp.async.wait_group %0;" :: "n"(n) : "memory")
#define PAIRBAR(id) asm volatile("bar.sync %0, 64;" :: "r"(id) : "memory")
#define FENCE_ACQ() asm volatile("fence.acq_rel.gpu;" ::: "memory")

__device__ __forceinline__ void mma16816(float* d, u32 a0, u32 a1, u32 a2, u32 a3,
                                         u32 b0, u32 b1) {
    asm volatile(
        "mma.sync.aligned.m16n8k16.row.col.f32.f16.f16.f32 "
        "{%0,%1,%2,%3}, {%4,%5,%6,%7}, {%8,%9}, {%0,%1,%2,%3};"
        : "+f"(d[0]), "+f"(d[1]), "+f"(d[2]), "+f"(d[3])
        : "r"(a0), "r"(a1), "r"(a2), "r"(a3), "r"(b0), "r"(b1));
}

__device__ __forceinline__ void bar_arrive(int tile) {
    __syncthreads();
    if (threadIdx.x == 0)
        asm volatile("red.release.gpu.global.add.u32 [%0], %1;"
                     :: "l"(&g_barc[tile * 32]), "r"(1u) : "memory");
}
__device__ __forceinline__ void bar_wait(int tile, unsigned target) {
    if (threadIdx.x == 0) {
        unsigned v;
        do {
            asm volatile("ld.acquire.gpu.global.u32 %0, [%1];"
                         : "=r"(v) : "l"(&g_barc[tile * 32]));
        } while (v < target);
    }
    __syncthreads();
}
__device__ __forceinline__ void flag_rel(unsigned* f, unsigned tag) {
    asm volatile("st.release.gpu.global.u32 [%0], %1;" :: "l"(f), "r"(tag) : "memory");
}
__device__ __forceinline__ void poll1(const unsigned* f, unsigned tag) {
    unsigned v;
    do { asm volatile("ld.volatile.global.u32 %0, [%1];" : "=r"(v) : "l"(f)); } while (v < tag);
}

__device__ __forceinline__ u64 pack_frag(const float* wr, int k0) {
    __half a = __float2half(wr[k0]),     b = __float2half(wr[k0 + 1]);
    __half c = __float2half(wr[k0 + 8]), d = __float2half(wr[k0 + 9]);
    return (u64)__half_as_ushort(a) | ((u64)__half_as_ushort(b) << 16)
         | ((u64)__half_as_ushort(c) << 32) | ((u64)__half_as_ushort(d) << 48);
}

// ---------------- prep ----------------
__global__ void prep_kernel(const float* __restrict__ W_unpack,
                            const float* __restrict__ Wih0,
                            const float* __restrict__ Whh0,
                            const float* __restrict__ bih0, const float* __restrict__ bhh0,
                            const float* __restrict__ Wih1,
                            const float* __restrict__ Whh1,
                            const float* __restrict__ bih1, const float* __restrict__ bhh1,
                            const float* __restrict__ gamma_a, const float* __restrict__ beta_a,
                            const float* __restrict__ Wa,
                            const float* __restrict__ gamma_w, const float* __restrict__ beta_w,
                            const float* __restrict__ Ww) {
    int i = blockIdx.x * blockDim.x + threadIdx.x;
    if (i < 65536) {
        int q = i >> 12, c = (i >> 8) & 15, ntp = (i >> 6) & 3, lane = (i >> 1) & 31, hs = i & 1;
        int nt = ntp * 2 + hs;
        int nloc = nt * 8 + (lane >> 2);
        int j, gate;
        if (nloc < 32) { j = nloc >> 1; gate = (nloc & 1) ? 1 : 0; }
        else { j = (nloc - 32) >> 1; gate = (nloc & 1) ? 3 : 2; }
        int orig = gate * 256 + q * 16 + j;
        g_frag0[i] = pack_frag(Whh0 + orig * 256, c * 16 + (lane & 3) * 2);
    }
    if (i < 131072) {
        int q = i >> 13, c = (i >> 8) & 31, ntp = (i >> 6) & 3, lane = (i >> 1) & 31, hs = i & 1;
        int nt = ntp * 2 + hs;
        int nloc = nt * 8 + (lane >> 2);
        int j, gate;
        if (nloc < 32) { j = nloc >> 1; gate = (nloc & 1) ? 1 : 0; }
        else { j = (nloc - 32) >> 1; gate = (nloc & 1) ? 3 : 2; }
        int orig = gate * 256 + q * 16 + j;
        const float* src = (c < 16) ? Wih1 : Whh1;
        g_frag1[i] = pack_frag(src + orig * 256, (c & 15) * 16 + (lane & 3) * 2);
    }
    if (i < 1024) {
        int j = i >> 2, comp = i & 3;
        float4 v;
        if (comp == 0)
            v = make_float4(bih0[j] + bhh0[j], bih0[256 + j] + bhh0[256 + j],
                            bih0[512 + j] + bhh0[512 + j], bih0[768 + j] + bhh0[768 + j]);
        else if (comp == 1)
            v = make_float4(Wih0[j * 2], Wih0[(256 + j) * 2],
                            Wih0[(512 + j) * 2], Wih0[(768 + j) * 2]);
        else if (comp == 2)
            v = make_float4(Wih0[j * 2 + 1], Wih0[(256 + j) * 2 + 1],
                            Wih0[(512 + j) * 2 + 1], Wih0[(768 + j) * 2 + 1]);
        else
            v = make_float4(bih1[j] + bhh1[j], bih1[256 + j] + bhh1[256 + j],
                            bih1[512 + j] + bhh1[512 + j], bih1[768 + j] + bhh1[768 + j]);
        g_epi[i] = v;
    }
    if (i < 128 * 256) {
        int k = i >> 8, j = i & 255;
        g_Wup[i] = W_unpack[j * 128 + k];
    }
    if (i < 256) {
        g_hA1[i] = gamma_a[i] * Wa[i];
        g_hW1[i] = gamma_w[i] * Ww[i];
    }
    if (i < 4) {
        float sA = 0.f, sW = 0.f;
        for (int j = i * 64; j < i * 64 + 64; j++) {
            sA += gamma_a[j] * Wa[j];
            sW += gamma_w[j] * Ww[j];
        }
        g_GAg[i] = sA;  g_GWg[i] = sW;
    }
    if (i == 4) {
        float tA = 0.f, tW = 0.f;
        for (int j = 0; j < 256; j++) {
            tA += beta_a[j] * Wa[j];
            tW += beta_w[j] * Ww[j];
        }
        g_BAt[0] = tA;  g_BWt[0] = tW;
    }
    if (i < TILES * 32) {
        g_flagA[i] = 0u;  g_flagB[i] = 0u;  g_barc[i] = 0u;
    }
}

// frag-permuted copy (prologue only): stage (row-major [128][16] halves) -> frag cells
__device__ __forceinline__ void copy_frag_out(u32 stage, uint4* dst, int t) {
    if (t < 256) {
        int m16 = t >> 5, l = t & 31;
        u32 s0 = stage + ((u32)((m16 * 16 + (l >> 2)) * 16 + 2 * (l & 3))) * 2;
        u32 a0, a1, a2, a3;
        asm volatile("ld.shared.b32 %0, [%1];"       : "=r"(a0) : "r"(s0));
        asm volatile("ld.shared.b32 %0, [%1+256];"   : "=r"(a1) : "r"(s0));
        asm volatile("ld.shared.b32 %0, [%1+16];"    : "=r"(a2) : "r"(s0));
        asm volatile("ld.shared.b32 %0, [%1+272];"   : "=r"(a3) : "r"(s0));
        asm volatile("st.global.cg.v4.b32 [%0], {%1,%2,%3,%4};"
                     :: "l"(dst + t), "r"(a0), "r"(a1), "r"(a2), "r"(a3));
    }
}

// consume one chunk: A from pair smem buf, B from smem frag region, 4 MMAs
__device__ __forceinline__ void chunk_mma(u32 abuf, u32 bbase, int c, int wn, int lane,
                                          float dm[4][4]) {
    uint4 av;
    asm volatile("ld.shared.v4.b32 {%0,%1,%2,%3}, [%4];"
                 : "=r"(av.x), "=r"(av.y), "=r"(av.z), "=r"(av.w)
                 : "r"(abuf + c * 512 + lane * 16));
#pragma unroll
    for (int pp = 0; pp < 2; pp++) {
        int p = wn + 2 * pp;
        u32 b0, b1, b2, b3;
        asm volatile("ld.shared.v4.b32 {%0,%1,%2,%3}, [%4];"
                     : "=r"(b0), "=r"(b1), "=r"(b2), "=r"(b3)
                     : "r"(bbase + (c * 4 + p) * 512 + lane * 16));
        mma16816(dm[pp * 2],     av.x, av.y, av.z, av.w, b0, b1);
        mma16816(dm[pp * 2 + 1], av.x, av.y, av.z, av.w, b2, b3);
    }
}

// ---------------- main ----------------
__global__ __launch_bounds__(NT, 1)
void gen_kernel(const float* __restrict__ noise,
                const float* __restrict__ b_unpack,
                const float* __restrict__ ba, const float* __restrict__ bw,
                int T, float* __restrict__ out) {
    extern __shared__ char smem[];
    const u32 sbase = smem_u32_of(smem);
    const int t = threadIdx.x;
    const int w = t >> 5, lane = t & 31;
    const int wq = w & 7;
    const int wn = w >> 3;
    const int tile = blockIdx.x >> 4;
    const int q = blockIdx.x & 15;
    const int m0 = wq * 16;
    const int r1 = m0 + (lane >> 2);
    const float bav = __ldg(ba), bwv = __ldg(bw);

    const u32 h0buf = sbase + H0B + wq * 16 * 512;   // pair-private, 8KB
    const u32 h1buf = sbase + H1B + wq * 16 * 512;
    float2* sc = (float2*)(smem + SC_OFF);
    const int pairbar = 1 + wq;

    uint4* h0cells = &g_h0frag[(tile * 16 + q) * 256];
    uint4* h1cells0 = &g_h1frag[0][(tile * 16 + q) * 256];
    uint4* h1cells1 = &g_h1frag[1][(tile * 16 + q) * 256];
    unsigned* flagA = &g_flagA[tile * 32 + q];
    unsigned* flagB = &g_flagB[tile * 32 + q];

    // shuffle-pack constants
    const int s3 = lane & 3, gb = lane & ~3;
    const int tsel = s3 >> 1;
    const int saL = gb | ((2 * s3) & 3);
    const int sbL = gb | ((2 * s3 + 1) & 3);

    // per-thread head consts for GN partials
    const int jg0 = q * 16 + 8 * wn + s3;
    const int jg1 = jg0 + 4;
    const float gaj0 = __ldg(&g_hA1[jg0]), gaj1 = __ldg(&g_hA1[jg1]);
    const float gwj0 = __ldg(&g_hW1[jg0]), gwj1 = __ldg(&g_hW1[jg1]);
    const float gagC = g_GAg[lane >> 3], gwgC = g_GWg[lane >> 3];
    const float BAt = g_BAt[0], BWt = g_BWt[0];

    if (t < 256) ((float*)sc)[t] = 0.f;

    // weights -> SMEM (fragment-ordered)
    for (int u = t; u < 2048; u += NT)
        CP16(sbase + B0_OFF + u * 16, (const char*)(g_frag0 + q * 4096) + u * 16);
    for (int u = t; u < 4096; u += NT)
        CP16(sbase + B1_OFF + u * 16, (const char*)(g_frag1 + q * 8192) + u * 16);
    CP_COMMIT();

    // noise + idea GEMV (H0B region as float scratch)
    float* nf = (float*)(smem + H0B);
    for (int i = t; i < 128 * 128; i += NT)
        nf[i] = __ldg(&noise[(size_t)(tile * 128) * 128 + i]);
    __syncthreads();
    float ideav[16];
    if (t < 128) {
#pragma unroll
        for (int j = 0; j < 16; j++) ideav[j] = __ldg(&b_unpack[q * 16 + j]);
        for (int k = 0; k < 128; k++) {
            float nv = nf[t * 128 + k];
            const float* wr = &g_Wup[k * 256 + q * 16];
#pragma unroll
            for (int j = 0; j < 16; j++) ideav[j] = fmaf(nv, __ldg(&wr[j]), ideav[j]);
        }
    }
    __syncthreads();
    // stage idea (row-major) into H1B+8192 then frag-copy out
    const u32 pstage = sbase + H1B + 8192;
    if (t < 128) {
#pragma unroll
        for (int j = 0; j < 16; j++) {
            float v = ideav[j];
            float e = (v > 0.f) ? v : (expf(v) - 1.f);
            asm volatile("st.global.cg.f32 [%0], %1;"
                :: "l"(&g_h0f[(size_t)(tile * 128 + t) * 256 + q * 16 + j]), "f"(e));
            unsigned short hs = __half_as_ushort(__float2half(e));
            asm volatile("st.shared.u16 [%0], %1;" :: "r"(pstage + (t * 16 + j) * 2), "h"(hs));
        }
    }
    __syncthreads();
    copy_frag_out(pstage, h0cells, t);
    CP_WAITALL();          // weights landed
    bar_arrive(tile);      // E0
    bar_wait(tile, 16);

    // c-state init
    float c0s[2][2], c1s[2][2];
#pragma unroll
    for (int tt = 0; tt < 2; tt++) {
        int jg = q * 16 + 8 * wn + 4 * tt + s3;
        float va, vb;
        asm volatile("ld.global.cg.f32 %0, [%1];" : "=f"(va)
                     : "l"(&g_h0f[(size_t)(tile * 128 + r1) * 256 + jg]));
        asm volatile("ld.global.cg.f32 %0, [%1];" : "=f"(vb)
                     : "l"(&g_h0f[(size_t)(tile * 128 + r1 + 8) * 256 + jg]));
        c0s[0][tt] = va;  c0s[1][tt] = vb;
        c1s[0][tt] = 0.f; c1s[1][tt] = 0.f;
    }

    // zero h1 bufs and fill h0 bufs
    {
        uint4 z = make_uint4(0, 0, 0, 0);
        uint4* hz = (uint4*)(smem + H1B);
        for (int i = t; i < 4096; i += NT) hz[i] = z;
    }
    if (wn == 0) {
        for (int c = 0; c < 16; c++)
            CP16(h0buf + c * 512 + lane * 16,
                 (const char*)(g_h0frag + (tile * 16 + c) * 256 + wq * 32 + lane));
        CP_COMMIT();
        CP_WAITALL();
    }
    __syncthreads();

    // prologue hoisted L0
    float dm0[4][4];
#pragma unroll
    for (int n = 0; n < 4; n++) { dm0[n][0]=dm0[n][1]=dm0[n][2]=dm0[n][3]=0.f; }
#pragma unroll
    for (int c = 0; c < 16; c++)
        chunk_mma(h0buf, sbase + B0_OFF, c, wn, lane, dm0);
    __syncthreads();

    for (int step = 0; step < T; ++step) {
        const int par = step & 1;
        const unsigned tag = (unsigned)(step + 1);
        uint4* h1cells = par ? h1cells1 : h1cells0;

        // ===== 1. L0 epilogue -> shuffle-pack -> direct frag STG =====
        {
            float2 cdA = sc[r1], cdB = sc[r1 + 8];
            float hf[2][2];
#pragma unroll
            for (int tt = 0; tt < 2; tt++) {
                int jg = q * 16 + 8 * wn + 4 * tt + s3;
                float4 e0 = __ldg(&g_epi[jg * 4 + 0]);
                float4 ea = __ldg(&g_epi[jg * 4 + 1]);
                float4 eb = __ldg(&g_epi[jg * 4 + 2]);
#pragma unroll
                for (int ri = 0; ri < 2; ri++) {
                    float2 cd = ri ? cdB : cdA;
                    float gi = dm0[tt][2*ri]     + e0.x + ea.x * cd.x + eb.x * cd.y;
                    float gf = dm0[tt][2*ri+1]   + e0.y + ea.y * cd.x + eb.y * cd.y;
                    float gg = dm0[2+tt][2*ri]   + e0.z + ea.z * cd.x + eb.z * cd.y;
                    float go = dm0[2+tt][2*ri+1] + e0.w + ea.w * cd.x + eb.w * cd.y;
                    float cn = fmaf(sig_fast(gf), c0s[ri][tt], sig_fast(gi) * tanh_fast(gg));
                    c0s[ri][tt] = cn;
                    hf[ri][tt] = sig_fast(go) * tanh_fast(cn);
                }
            }
            u32 pk[2];
#pragma unroll
            for (int ri = 0; ri < 2; ri++) {
                float lo0 = __shfl_sync(FULLM, hf[ri][0], saL);
                float lo1 = __shfl_sync(FULLM, hf[ri][1], saL);
                float hi0 = __shfl_sync(FULLM, hf[ri][0], sbL);
                float hi1 = __shfl_sync(FULLM, hf[ri][1], sbL);
                float lo = tsel ? lo1 : lo0, hi = tsel ? hi1 : hi0;
                __half2 h2 = __floats2half2_rn(lo, hi);
                pk[ri] = *(u32*)&h2;
            }
            char* dst = (char*)(h0cells + wq * 32 + lane) + wn * 8;
            asm volatile("st.global.cg.v2.b32 [%0], {%1,%2};"
                         :: "l"(dst), "r"(pk[0]), "r"(pk[1]));
        }
        __syncthreads();                       // S1
        if (t == 0) flag_rel(flagA, tag);

        // ===== 2. partA: h1 bufs (refilled last step) + B1 chunks 16-31 =====
        float dm1[4][4];
#pragma unroll
        for (int n = 0; n < 4; n++) { dm1[n][0]=dm1[n][1]=dm1[n][2]=dm1[n][3]=0.f; }
#pragma unroll
        for (int b = 0; b < 4; b++) {
            if (wn == 0) {
                if (b == 0) CP_WAITGRP(3);
                else if (b == 1) CP_WAITGRP(2);
                else if (b == 2) CP_WAITGRP(1);
                else CP_WAITGRP(0);
            }
            PAIRBAR(pairbar);
#pragma unroll
            for (int k = 0; k < 4; k++) {
                int c = b * 4 + k;
                uint4 av;
                asm volatile("ld.shared.v4.b32 {%0,%1,%2,%3}, [%4];"
                             : "=r"(av.x), "=r"(av.y), "=r"(av.z), "=r"(av.w)
                             : "r"(h1buf + c * 512 + lane * 16));
#pragma unroll
                for (int pp = 0; pp < 2; pp++) {
                    int p = wn + 2 * pp;
                    u32 b0, b1, b2, b3;
                    asm volatile("ld.shared.v4.b32 {%0,%1,%2,%3}, [%4];"
                                 : "=r"(b0), "=r"(b1), "=r"(b2), "=r"(b3)
                                 : "r"(sbase + B1_OFF + ((c + 16) * 4 + p) * 512 + lane * 16));
                    mma16816(dm1[pp * 2],     av.x, av.y, av.z, av.w, b0, b1);
                    mma16816(dm1[pp * 2 + 1], av.x, av.y, av.z, av.w, b2, b3);
                }
            }
        }

        // ===== 3. partB: poll flags per batch, cp.async own cells, consume =====
        if (wn == 0) {
            if (lane == 0) { poll1(&g_flagA[tile*32+0], tag); poll1(&g_flagA[tile*32+1], tag);
                             poll1(&g_flagA[tile*32+2], tag); poll1(&g_flagA[tile*32+3], tag); }
            __syncwarp(); FENCE_ACQ();
#pragma unroll
            for (int c = 0; c < 4; c++)
                CP16(h0buf + c * 512 + lane * 16,
                     (const char*)(g_h0frag + (tile * 16 + c) * 256 + wq * 32 + lane));
            CP_COMMIT();
            if (lane == 0) { poll1(&g_flagA[tile*32+4], tag); poll1(&g_flagA[tile*32+5], tag);
                             poll1(&g_flagA[tile*32+6], tag); poll1(&g_flagA[tile*32+7], tag); }
            __syncwarp(); FENCE_ACQ();
#pragma unroll
            for (int c = 4; c < 8; c++)
                CP16(h0buf + c * 512 + lane * 16,
                     (const char*)(g_h0frag + (tile * 16 + c) * 256 + wq * 32 + lane));
            CP_COMMIT();
        }
#pragma unroll
        for (int b = 0; b < 4; b++) {
            if (wn == 0 && b + 2 < 4) {
                int cb = (b + 2) * 4;
                if (lane == 0) { poll1(&g_flagA[tile*32+cb], tag); poll1(&g_flagA[tile*32+cb+1], tag);
                                 poll1(&g_flagA[tile*32+cb+2], tag); poll1(&g_flagA[tile*32+cb+3], tag); }
                __syncwarp(); FENCE_ACQ();
#pragma unroll
                for (int k = 0; k < 4; k++)
                    CP16(h0buf + (cb + k) * 512 + lane * 16,
                         (const char*)(g_h0frag + (tile * 16 + cb + k) * 256 + wq * 32 + lane));
                CP_COMMIT();
            }
            if (wn == 0) {
                if (b == 0) CP_WAITGRP(2);
                else if (b == 1) CP_WAITGRP(2);
                else if (b == 2) CP_WAITGRP(1);
                else CP_WAITGRP(0);
            }
            PAIRBAR(pairbar);
#pragma unroll
            for (int k = 0; k < 4; k++)
                chunk_mma(h0buf, sbase + B1_OFF, b * 4 + k, wn, lane, dm1);
        }

        // ===== 4. L1 epilogue -> shuffle-pack STG + GN partials =====
        {
            float hf[2][2];
#pragma unroll
            for (int tt = 0; tt < 2; tt++) {
                int jg = q * 16 + 8 * wn + 4 * tt + s3;
                float4 e3 = __ldg(&g_epi[jg * 4 + 3]);
#pragma unroll
                for (int ri = 0; ri < 2; ri++) {
                    float gi = dm1[tt][2*ri]     + e3.x;
                    float gf = dm1[tt][2*ri+1]   + e3.y;
                    float gg = dm1[2+tt][2*ri]   + e3.z;
                    float go = dm1[2+tt][2*ri+1] + e3.w;
                    float cn = fmaf(sig_fast(gf), c1s[ri][tt], sig_fast(gi) * tanh_fast(gg));
                    c1s[ri][tt] = cn;
                    hf[ri][tt] = sig_fast(go) * tanh_fast(cn);
                }
            }
            u32 pk[2];
#pragma unroll
            for (int ri = 0; ri < 2; ri++) {
                float lo0 = __shfl_sync(FULLM, hf[ri][0], saL);
                float lo1 = __shfl_sync(FULLM, hf[ri][1], saL);
                float hi0 = __shfl_sync(FULLM, hf[ri][0], sbL);
                float hi1 = __shfl_sync(FULLM, hf[ri][1], sbL);
                float lo = tsel ? lo1 : lo0, hi = tsel ? hi1 : hi0;
                __half2 h2 = __floats2half2_rn(lo, hi);
                pk[ri] = *(u32*)&h2;
            }
            char* dst = (char*)(h1cells + wq * 32 + lane) + wn * 8;
            asm volatile("st.global.cg.v2.b32 [%0], {%1,%2};"
                         :: "l"(dst), "r"(pk[0]), "r"(pk[1]));
            // GN partials per (row, q*2+wn): 4-lane group reduce
#pragma unroll
            for (int ri = 0; ri < 2; ri++) {
                float f0 = hf[ri][0], f1 = hf[ri][1];
                float sh  = f0 + f1;
                float sh2 = fmaf(f0, f0, f1 * f1);
                float sA  = f0 * gaj0 + f1 * gaj1;
                float sW  = f0 * gwj0 + f1 * gwj1;
#pragma unroll
                for (int off = 1; off < 4; off <<= 1) {
                    sh  += __shfl_xor_sync(FULLM, sh,  off);
                    sh2 += __shfl_xor_sync(FULLM, sh2, off);
                    sA  += __shfl_xor_sync(FULLM, sA,  off);
                    sW  += __shfl_xor_sync(FULLM, sW,  off);
                }
                if (s3 == 0) {
                    int row = r1 + 8 * ri;
                    float4* pp4 = &g_part2[(size_t)(tile * 128 + row) * 32 + q * 2 + wn];
                    asm volatile("st.global.cg.v4.f32 [%0], {%1,%2,%3,%4};"
                                 :: "l"(pp4), "f"(sh), "f"(sh2), "f"(sA), "f"(sW));
                }
            }
        }
        __syncthreads();                       // S2
        if (t == 0) flag_rel(flagB, tag);

        // ===== 5. hoisted L0 for step+1 (h0 bufs hold h0new) =====
#pragma unroll
        for (int n = 0; n < 4; n++) { dm0[n][0]=dm0[n][1]=dm0[n][2]=dm0[n][3]=0.f; }
#pragma unroll
        for (int c = 0; c < 16; c++)
            chunk_mma(h0buf, sbase + B0_OFF, c, wn, lane, dm0);

        // ===== 6. combine: poll all flagB, compute coords =====
        {
            for (;;) {
                unsigned v = 0xffffffffu;
                if (lane < 16)
                    asm volatile("ld.volatile.global.u32 %0, [%1];"
                                 : "=r"(v) : "l"(&g_flagB[tile * 32 + lane]));
                if (__all_sync(FULLM, v >= tag)) break;
            }
            FENCE_ACQ();
#pragma unroll 2
            for (int ps = 0; ps < 8; ps++) {
                int row = w * 8 + ps;
                float4 P;
                asm volatile("ld.global.cg.v4.f32 {%0,%1,%2,%3}, [%4];"
                             : "=f"(P.x), "=f"(P.y), "=f"(P.z), "=f"(P.w)
                             : "l"(&g_part2[(size_t)(tile * 128 + row) * 32 + lane]));
                float sh = P.x, sh2 = P.y, sA = P.z, sW = P.w;
#pragma unroll
                for (int off = 1; off < 8; off <<= 1) {
                    sh  += __shfl_xor_sync(FULLM, sh,  off);
                    sh2 += __shfl_xor_sync(FULLM, sh2, off);
                    sA  += __shfl_xor_sync(FULLM, sA,  off);
                    sW  += __shfl_xor_sync(FULLM, sW,  off);
                }
                float mu   = sh * (1.f / 64.f);
                float var  = sh2 * (1.f / 64.f) - mu * mu;
                float rstd = rsqrtf(var + EPSG);
                float vA = rstd * (sA - mu * gagC);
                float vW = rstd * (sW - mu * gwgC);
                if (lane & 7) { vA = 0.f; vW = 0.f; }
#pragma unroll
                for (int off = 8; off < 32; off <<= 1) {
                    vA += __shfl_xor_sync(FULLM, vA, off);
                    vW += __shfl_xor_sync(FULLM, vW, off);
                }
                if (lane == 0) {
                    float ang = tanh_fast(vA + BAt + bav);
                    float wdt = sig_fast(vW + BWt + bwv);
                    sc[row] = make_float2(ang, wdt);
                    if (q == (row >> 3)) {
                        float2* op = (float2*)(out + ((size_t)(tile * 128 + row) * T + step) * 2);
                        *op = make_float2(ang, wdt);
                    }
                }
            }
        }

        // ===== 7. refill h1 bufs for next step's partA =====
        if (wn == 0) {
            const uint4* src = (par ? g_h1frag[1] : g_h1frag[0]);
#pragma unroll
            for (int b = 0; b < 4; b++) {
#pragma unroll
                for (int k = 0; k < 4; k++) {
                    int c = b * 4 + k;
                    CP16(h1buf + c * 512 + lane * 16,
                         (const char*)(src + (tile * 16 + c) * 256 + wq * 32 + lane));
                }
                CP_COMMIT();
            }
        }
        __syncthreads();                       // S3
    }
}

extern "C" void kernel_launch(void* const* d_in, const int* in_sizes, int n_in,
                              void* d_out, int out_size) {
    const float* noise    = (const float*)d_in[0];
    const float* W_unpack = (const float*)d_in[1];
    const float* b_unpack = (const float*)d_in[2];
    const float* Wih0     = (const float*)d_in[3];
    const float* Whh0     = (const float*)d_in[4];
    const float* bih0     = (const float*)d_in[5];
    const float* bhh0     = (const float*)d_in[6];
    const float* Wih1     = (const float*)d_in[7];
    const float* Whh1     = (const float*)d_in[8];
    const float* bih1     = (const float*)d_in[9];
    const float* bhh1     = (const float*)d_in[10];
    const float* gamma_a  = (const float*)d_in[11];
    const float* beta_a   = (const float*)d_in[12];
    const float* Wa       = (const float*)d_in[13];
    const float* ba       = (const float*)d_in[14];
    const float* gamma_w  = (const float*)d_in[15];
    const float* beta_w   = (const float*)d_in[16];
    const float* Ww       = (const float*)d_in[17];
    const float* bw       = (const float*)d_in[18];
    (void)in_sizes; (void)n_in;

    int T = out_size / (BB * 2);

    cudaFuncSetAttribute(gen_kernel, cudaFuncAttributeMaxDynamicSharedMemorySize, SMEM_TOTAL);
    prep_kernel<<<512, 256>>>(W_unpack, Wih0, Whh0, bih0, bhh0, Wih1, Whh1, bih1, bhh1,
                              gamma_a, beta_a, Wa, gamma_w, beta_w, Ww);
    gen_kernel<<<NCTA, NT, SMEM_TOTAL>>>(noise, b_unpack, ba, bw, T, (float*)d_out);
}